// round 1
// baseline (speedup 1.0000x reference)
#include <cuda_runtime.h>
#include <cstdint>
#include <cfloat>
#include <climits>

// Problem constants (fixed by the dataset)
#define NN   100000      // nodes
#define EE   400000      // edges per relation
#define RR   4           // relations
#define DIN  128
#define COLS 640         // R*128 (relation projections) + 128 (self-loop)
#define HMAX 8

// ---------------- device scratch (static, no allocation) ----------------
__device__ float g_B[128 * COLS];                       // packed weights [128,640]
__device__ float g_WhAll[(size_t)NN * COLS];            // GEMM output   [N,640]
__device__ float g_h1[(size_t)NN * DIN];                // layer-1 output / layer-1 acc
__device__ float g_el[(size_t)RR * NN * HMAX];
__device__ float g_er[(size_t)RR * NN * HMAX];
__device__ int   g_m[(size_t)RR * NN * HMAX];           // ordered-int segment max
__device__ float g_den[(size_t)RR * NN * HMAX];         // softmax denom -> reciprocal
__device__ float g_e[(size_t)RR * EE * HMAX];           // e, then ex, per edge/head

// ---------------- helpers ----------------
__device__ __forceinline__ int f2ord(float f) {
    int i = __float_as_int(f);
    return i >= 0 ? i : (i ^ 0x7FFFFFFF);
}
__device__ __forceinline__ float ord2f(int k) {
    return __int_as_float(k >= 0 ? k : (k ^ 0x7FFFFFFF));
}

// ---------------- pack weights: B[k,c] ----------------
__global__ void pack_B(const float* __restrict__ W, const float* __restrict__ loop_w) {
    int idx = blockIdx.x * blockDim.x + threadIdx.x;
    if (idx >= 128 * COLS) return;
    int k = idx / COLS, c = idx % COLS;
    float v;
    if (c < RR * 128) {
        int r = c >> 7, j = c & 127;
        v = W[((size_t)r << 14) + (size_t)k * 128 + j];
    } else {
        v = loop_w[(size_t)k * 128 + (c - RR * 128)];
    }
    g_B[idx] = v;
}

// ---------------- SGEMM: C[N,640] = A[N,128] * g_B[128,640] ----------------
// 64x64 block tile, BK=16, 256 threads, 4x4 per thread.
#define BM 64
#define BN 64
#define BK 16
__global__ __launch_bounds__(256) void sgemm640(const float* __restrict__ Ain, int M) {
    const float* A = Ain ? Ain : g_h1;
    __shared__ float As[BK][BM + 4];
    __shared__ float Bs[BK][BN];
    int bn = blockIdx.x, bm = blockIdx.y;
    int tid = threadIdx.x;
    int tx = tid & 15, ty = tid >> 4;

    float acc[4][4] = {};
    int a_r = tid >> 2;              // 0..63
    int a_k = (tid & 3) * 4;         // 0,4,8,12
    int b_k = tid >> 4;              // 0..15
    int b_c = (tid & 15) * 4;        // 0..60
    int row0 = bm * BM;

    for (int k0 = 0; k0 < 128; k0 += BK) {
        float4 av = make_float4(0.f, 0.f, 0.f, 0.f);
        int gr = row0 + a_r;
        if (gr < M) av = *(const float4*)(A + (size_t)gr * 128 + k0 + a_k);
        As[a_k + 0][a_r] = av.x;
        As[a_k + 1][a_r] = av.y;
        As[a_k + 2][a_r] = av.z;
        As[a_k + 3][a_r] = av.w;
        float4 bv = *(const float4*)(g_B + (size_t)(k0 + b_k) * COLS + bn * BN + b_c);
        *(float4*)(&Bs[b_k][b_c]) = bv;
        __syncthreads();
#pragma unroll
        for (int kk = 0; kk < BK; kk++) {
            float a[4], b[4];
#pragma unroll
            for (int i = 0; i < 4; i++) a[i] = As[kk][ty * 4 + i];
#pragma unroll
            for (int j = 0; j < 4; j++) b[j] = Bs[kk][tx * 4 + j];
#pragma unroll
            for (int i = 0; i < 4; i++)
#pragma unroll
                for (int j = 0; j < 4; j++) acc[i][j] += a[i] * b[j];
        }
        __syncthreads();
    }
#pragma unroll
    for (int i = 0; i < 4; i++) {
        int gr = row0 + ty * 4 + i;
        if (gr < M) {
            float4 v = make_float4(acc[i][0], acc[i][1], acc[i][2], acc[i][3]);
            *(float4*)(g_WhAll + (size_t)gr * COLS + bn * BN + tx * 4) = v;
        }
    }
}

// ---------------- acc init: acc = WhAll[:,512:640] + bias ----------------
__global__ void init_acc(const float* __restrict__ bias, float* accp) {
    float* acc = accp ? accp : g_h1;
    int idx = blockIdx.x * blockDim.x + threadIdx.x;
    if (idx >= NN * DIN) return;
    int i = idx >> 7, j = idx & 127;
    acc[idx] = g_WhAll[(size_t)i * COLS + RR * 128 + j] + bias[j];
}

// ---------------- init m / denom ----------------
__global__ void init_md(int total) {
    int idx = blockIdx.x * blockDim.x + threadIdx.x;
    if (idx >= total) return;
    g_m[idx] = INT_MIN;
    g_den[idx] = 0.f;
}

// ---------------- el/er: per (r,node) reduction over Dh within each head ----
__global__ __launch_bounds__(128) void elr_kernel(const float* __restrict__ al,
                                                  const float* __restrict__ ar,
                                                  int H, int Dh) {
    int i = blockIdx.x;
    int r = blockIdx.y;
    int t = threadIdx.x;  // 0..127
    float v = g_WhAll[(size_t)i * COLS + r * 128 + t];
    __shared__ float sl[128], sr[128];
    sl[t] = v * al[r * 128 + t];
    sr[t] = v * ar[r * 128 + t];
    __syncthreads();
    for (int off = Dh >> 1; off > 0; off >>= 1) {
        if ((t & (Dh - 1)) < off) {
            sl[t] += sl[t + off];
            sr[t] += sr[t + off];
        }
        __syncthreads();
    }
    if ((t & (Dh - 1)) == 0) {
        int head = t / Dh;
        size_t o = ((size_t)r * NN + i) * H + head;
        g_el[o] = sl[t];
        g_er[o] = sr[t];
    }
}

// ---------------- pass A: e = leaky(el[src]+er[dst]); segment max -----------
__global__ void edge_pass_max(const int* __restrict__ src, const int* __restrict__ dst,
                              int H) {
    int idx = blockIdx.x * blockDim.x + threadIdx.x;  // r*E + e
    if (idx >= RR * EE) return;
    int s = src[idx], d = dst[idx];
    int r = idx / EE;
    size_t so = ((size_t)r * NN + s) * H;
    size_t dvo = ((size_t)r * NN + d) * H;
    for (int h = 0; h < H; h++) {
        float e = g_el[so + h] + g_er[dvo + h];
        e = e > 0.f ? e : 0.2f * e;
        g_e[(size_t)idx * H + h] = e;
        atomicMax(&g_m[dvo + h], f2ord(e));
    }
}

// ---------------- pass B: ex = exp(e - m); denom += ex ----------------------
__global__ void edge_pass_exp(const int* __restrict__ dst, int H) {
    int idx = blockIdx.x * blockDim.x + threadIdx.x;
    if (idx >= RR * EE) return;
    int d = dst[idx];
    int r = idx / EE;
    size_t dvo = ((size_t)r * NN + d) * H;
    for (int h = 0; h < H; h++) {
        float mf = ord2f(g_m[dvo + h]);
        float ex = expf(g_e[(size_t)idx * H + h] - mf);
        g_e[(size_t)idx * H + h] = ex;
        atomicAdd(&g_den[dvo + h], ex);
    }
}

// ---------------- reciprocal of denom ----------------
__global__ void rcp_den(int total) {
    int idx = blockIdx.x * blockDim.x + threadIdx.x;
    if (idx >= total) return;
    g_den[idx] = 1.0f / g_den[idx];
}

// ---------------- pass C: acc[dst] += alpha * Wh[src] (warp per edge) -------
__global__ __launch_bounds__(256) void edge_aggregate(const int* __restrict__ src,
                                                      const int* __restrict__ dst,
                                                      float* accp, int H, int Dh) {
    float* acc = accp ? accp : g_h1;
    int gw = (blockIdx.x * blockDim.x + threadIdx.x) >> 5;  // global warp = r*E + e
    int lane = threadIdx.x & 31;
    if (gw >= RR * EE) return;
    int s = src[gw], d = dst[gw];
    int r = gw / EE;
    int head = (lane * 4) / Dh;
    float alpha = g_e[(size_t)gw * H + head] *
                  g_den[((size_t)r * NN + d) * H + head];
    float4 w = *(const float4*)(g_WhAll + (size_t)s * COLS + r * 128 + lane * 4);
    float* p = acc + (size_t)d * DIN + lane * 4;
    asm volatile("red.global.add.v4.f32 [%0], {%1,%2,%3,%4};" ::"l"(p),
                 "f"(w.x * alpha), "f"(w.y * alpha), "f"(w.z * alpha),
                 "f"(w.w * alpha)
                 : "memory");
}

// ---------------- relu in place on g_h1 ----------------
__global__ void relu_h1() {
    int idx = blockIdx.x * blockDim.x + threadIdx.x;
    if (idx >= NN * DIN) return;
    float v = g_h1[idx];
    g_h1[idx] = v > 0.f ? v : 0.f;
}

// ---------------- host-side layer driver ----------------
static void run_layer(const float* h_in,  // nullptr => g_h1
                      const int* src, const int* dst, const float* W,
                      const float* al, const float* ar, const float* loop_w,
                      const float* bias, int H, int Dh,
                      float* acc,  // nullptr => g_h1
                      bool do_relu) {
    const int mdTotal = RR * NN * H;

    pack_B<<<(128 * COLS + 255) / 256, 256>>>(W, loop_w);
    sgemm640<<<dim3(COLS / BN, (NN + BM - 1) / BM), 256>>>(h_in, NN);
    init_acc<<<(NN * DIN + 255) / 256, 256>>>(bias, acc);
    init_md<<<(mdTotal + 255) / 256, 256>>>(mdTotal);
    elr_kernel<<<dim3(NN, RR), 128>>>(al, ar, H, Dh);
    edge_pass_max<<<(RR * EE + 255) / 256, 256>>>(src, dst, H);
    edge_pass_exp<<<(RR * EE + 255) / 256, 256>>>(dst, H);
    rcp_den<<<(mdTotal + 255) / 256, 256>>>(mdTotal);
    {
        long long threads = (long long)RR * EE * 32;
        int blocks = (int)((threads + 255) / 256);
        edge_aggregate<<<blocks, 256>>>(src, dst, acc, H, Dh);
    }
    if (do_relu) relu_h1<<<(NN * DIN + 255) / 256, 256>>>();
}

extern "C" void kernel_launch(void* const* d_in, const int* in_sizes, int n_in,
                              void* d_out, int out_size) {
    const float* h   = (const float*)d_in[0];
    const int*   src = (const int*)d_in[1];
    const int*   dst = (const int*)d_in[2];
    const float* W1  = (const float*)d_in[3];
    const float* al1 = (const float*)d_in[4];
    const float* ar1 = (const float*)d_in[5];
    const float* lp1 = (const float*)d_in[6];
    const float* b1  = (const float*)d_in[7];
    const float* W2  = (const float*)d_in[8];
    const float* al2 = (const float*)d_in[9];
    const float* ar2 = (const float*)d_in[10];
    const float* lp2 = (const float*)d_in[11];
    const float* b2  = (const float*)d_in[12];
    float* out = (float*)d_out;

    // Layer 1: h -> g_h1 (H=8, Dh=16), relu
    run_layer(h, src, dst, W1, al1, ar1, lp1, b1, 8, 16, /*acc=*/nullptr, true);
    // Layer 2: g_h1 -> out (H=1, Dh=128), no activation
    run_layer(/*h_in=*/nullptr, src, dst, W2, al2, ar2, lp2, b2, 1, 128, out, false);

    (void)in_sizes; (void)n_in; (void)out_size;
}

// round 3
// speedup vs baseline: 1.2692x; 1.2692x over previous
#include <cuda_runtime.h>
#include <cstdint>

// Problem constants (fixed by the dataset)
#define NN   100000
#define EE   400000
#define RR   4
#define DIN  128
#define COLS 640         // R*128 + 128 self-loop
#define HMAX 8

// ---------------- device scratch (static, no allocation) ----------------
__device__ float g_Bt[COLS * DIN];                      // packed weights [c][k], tf32-rounded
__device__ float g_WhAll[(size_t)NN * COLS];            // GEMM output   [N,640]
__device__ float g_h1[(size_t)NN * DIN];                // layer-1 output / acc
__device__ float g_el[(size_t)RR * NN * HMAX];
__device__ float g_er[(size_t)RR * NN * HMAX];
__device__ float g_den[(size_t)RR * NN * HMAX];         // softmax denom -> reciprocal
__device__ float g_e[(size_t)RR * EE * HMAX];           // ex per edge/head

// ---------------- helpers ----------------
__device__ __forceinline__ float tf32_rn(float x) {
    uint32_t u;
    asm("cvt.rna.tf32.f32 %0, %1;" : "=r"(u) : "f"(x));
    return __uint_as_float(u);
}

__device__ __forceinline__ void mma_tf32(float* d, const uint32_t* a, const uint32_t* b) {
    asm volatile(
        "mma.sync.aligned.m16n8k8.row.col.f32.tf32.tf32.f32 "
        "{%0,%1,%2,%3}, {%4,%5,%6,%7}, {%8,%9}, {%0,%1,%2,%3};"
        : "+f"(d[0]), "+f"(d[1]), "+f"(d[2]), "+f"(d[3])
        : "r"(a[0]), "r"(a[1]), "r"(a[2]), "r"(a[3]), "r"(b[0]), "r"(b[1]));
}

// ---------------- pack weights transposed: g_Bt[c][k], tf32-rounded ----------------
__global__ void pack_Bt(const float* __restrict__ W, const float* __restrict__ loop_w) {
    int idx = blockIdx.x * blockDim.x + threadIdx.x;
    if (idx >= COLS * DIN) return;
    int c = idx >> 7, k = idx & 127;
    float v;
    if (c < RR * 128) {
        int r = c >> 7, j = c & 127;
        v = W[((size_t)r << 14) + (size_t)k * 128 + j];
    } else {
        v = loop_w[(size_t)k * 128 + (c - RR * 128)];
    }
    g_Bt[idx] = tf32_rn(v);
}

// ---------------- tf32 mma GEMM: C[M,640] = A[M,128] * g_Bt^T ----------------
// CTA tile 128x128, full K=128 in smem, 8 warps (4x2), warp tile 32x64.
#define LDS_PITCH 132
#define GEMM_SMEM (2 * 128 * LDS_PITCH * 4)
__global__ __launch_bounds__(256, 1) void gemm_mma(const float* __restrict__ Ain, int M) {
    const float* A = Ain ? Ain : g_h1;
    extern __shared__ float sm[];
    float (*As)[LDS_PITCH] = (float(*)[LDS_PITCH])sm;
    float (*Bs)[LDS_PITCH] = (float(*)[LDS_PITCH])(sm + 128 * LDS_PITCH);

    int tid = threadIdx.x;
    int wid = tid >> 5, lane = tid & 31;
    int group = lane >> 2, tid4 = lane & 3;
    int warp_m = wid >> 1, warp_n = wid & 1;
    int bn = blockIdx.x, by = blockIdx.y;

    // ---- stage A tile (tf32-rounded) ----
    {
        int row = tid >> 1;
        int colb = (tid & 1) * 64;
        int grow = by * 128 + row;
        const float4* ap = (grow < M) ? (const float4*)(A + (size_t)grow * DIN + colb) : nullptr;
#pragma unroll
        for (int j = 0; j < 16; j++) {
            float4 v = ap ? __ldg(ap + j) : make_float4(0.f, 0.f, 0.f, 0.f);
            float4 t = make_float4(tf32_rn(v.x), tf32_rn(v.y), tf32_rn(v.z), tf32_rn(v.w));
            *(float4*)(&As[row][colb + j * 4]) = t;
        }
    }
    // ---- stage B tile (already tf32-rounded), Bs[n][k] ----
    {
        int row = tid >> 1;
        int colb = (tid & 1) * 64;
        const float4* bp = (const float4*)(g_Bt + (size_t)(bn * 128 + row) * DIN + colb);
#pragma unroll
        for (int j = 0; j < 16; j++)
            *(float4*)(&Bs[row][colb + j * 4]) = __ldg(bp + j);
    }
    __syncthreads();

    float acc[2][8][4] = {};
    int m0 = warp_m * 32;
    int n0 = warp_n * 64;

#pragma unroll
    for (int ks = 0; ks < 16; ks++) {
        int k0 = ks * 8;
        uint32_t afr[2][4];
#pragma unroll
        for (int mt = 0; mt < 2; mt++) {
            int mr = m0 + mt * 16;
            afr[mt][0] = __float_as_uint(As[mr + group][k0 + tid4]);
            afr[mt][1] = __float_as_uint(As[mr + group + 8][k0 + tid4]);
            afr[mt][2] = __float_as_uint(As[mr + group][k0 + tid4 + 4]);
            afr[mt][3] = __float_as_uint(As[mr + group + 8][k0 + tid4 + 4]);
        }
#pragma unroll
        for (int nt = 0; nt < 8; nt++) {
            int nc = n0 + nt * 8;
            uint32_t bfr[2];
            bfr[0] = __float_as_uint(Bs[nc + group][k0 + tid4]);
            bfr[1] = __float_as_uint(Bs[nc + group][k0 + tid4 + 4]);
            mma_tf32(acc[0][nt], afr[0], bfr);
            mma_tf32(acc[1][nt], afr[1], bfr);
        }
    }

    // ---- epilogue: float2 stores ----
#pragma unroll
    for (int mt = 0; mt < 2; mt++) {
        int row = by * 128 + m0 + mt * 16 + group;
#pragma unroll
        for (int nt = 0; nt < 8; nt++) {
            int col = bn * 128 + n0 + nt * 8 + tid4 * 2;
            if (row < M)
                *(float2*)(g_WhAll + (size_t)row * COLS + col) =
                    make_float2(acc[mt][nt][0], acc[mt][nt][1]);
            if (row + 8 < M)
                *(float2*)(g_WhAll + (size_t)(row + 8) * COLS + col) =
                    make_float2(acc[mt][nt][2], acc[mt][nt][3]);
        }
    }
}

// ---------------- acc init: acc = WhAll[:,512:640] + bias ----------------
__global__ void init_acc(const float* __restrict__ bias, float* accp) {
    float* acc = accp ? accp : g_h1;
    int idx = blockIdx.x * blockDim.x + threadIdx.x;
    if (idx >= NN * DIN) return;
    int i = idx >> 7, j = idx & 127;
    acc[idx] = g_WhAll[(size_t)i * COLS + RR * 128 + j] + bias[j];
}

// ---------------- init denom ----------------
__global__ void init_den(int total) {
    int idx = blockIdx.x * blockDim.x + threadIdx.x;
    if (idx >= total) return;
    g_den[idx] = 0.f;
}

// ---------------- el/er per (r,node) ----------------
__global__ __launch_bounds__(128) void elr_kernel(const float* __restrict__ al,
                                                  const float* __restrict__ ar,
                                                  int H, int Dh) {
    int i = blockIdx.x;
    int r = blockIdx.y;
    int t = threadIdx.x;
    float v = g_WhAll[(size_t)i * COLS + r * 128 + t];
    __shared__ float sl[128], sr[128];
    sl[t] = v * al[r * 128 + t];
    sr[t] = v * ar[r * 128 + t];
    __syncthreads();
    for (int off = Dh >> 1; off > 0; off >>= 1) {
        if ((t & (Dh - 1)) < off) {
            sl[t] += sl[t + off];
            sr[t] += sr[t + off];
        }
        __syncthreads();
    }
    if ((t & (Dh - 1)) == 0) {
        int head = t / Dh;
        size_t o = ((size_t)r * NN + i) * H + head;
        g_el[o] = sl[t];
        g_er[o] = sr[t];
    }
}

// ---------------- edge pass: ex = exp(leaky(el[src]+er[dst])); denom += ex ------
// (segment-max dropped: exp(e)/sum(exp(e)) is algebraically identical and |e| is small)
__global__ void edge_pass_exp(const int* __restrict__ src, const int* __restrict__ dst,
                              int H) {
    int idx = blockIdx.x * blockDim.x + threadIdx.x;
    if (idx >= RR * EE) return;
    int s = src[idx], d = dst[idx];
    int r = idx / EE;
    size_t so = ((size_t)r * NN + s) * H;
    size_t dvo = ((size_t)r * NN + d) * H;
    for (int h = 0; h < H; h++) {
        float e = g_el[so + h] + g_er[dvo + h];
        e = e > 0.f ? e : 0.2f * e;
        float ex = expf(e);
        g_e[(size_t)idx * H + h] = ex;
        atomicAdd(&g_den[dvo + h], ex);
    }
}

// ---------------- reciprocal of denom ----------------
__global__ void rcp_den(int total) {
    int idx = blockIdx.x * blockDim.x + threadIdx.x;
    if (idx >= total) return;
    g_den[idx] = 1.0f / g_den[idx];
}

// ---------------- aggregate: acc[dst] += alpha * Wh[src] (warp per edge) --------
__global__ __launch_bounds__(256) void edge_aggregate(const int* __restrict__ src,
                                                      const int* __restrict__ dst,
                                                      float* accp, int H, int Dh) {
    float* acc = accp ? accp : g_h1;
    int gw = (blockIdx.x * blockDim.x + threadIdx.x) >> 5;
    int lane = threadIdx.x & 31;
    if (gw >= RR * EE) return;
    int s = src[gw], d = dst[gw];
    int r = gw / EE;
    int head = (lane * 4) / Dh;
    float alpha = g_e[(size_t)gw * H + head] *
                  g_den[((size_t)r * NN + d) * H + head];
    float4 w = *(const float4*)(g_WhAll + (size_t)s * COLS + r * 128 + lane * 4);
    float* p = acc + (size_t)d * DIN + lane * 4;
    asm volatile("red.global.add.v4.f32 [%0], {%1,%2,%3,%4};" ::"l"(p),
                 "f"(w.x * alpha), "f"(w.y * alpha), "f"(w.z * alpha), "f"(w.w * alpha)
                 : "memory");
}

// ---------------- relu in place on g_h1 ----------------
__global__ void relu_h1() {
    int idx = blockIdx.x * blockDim.x + threadIdx.x;
    if (idx >= NN * DIN) return;
    float v = g_h1[idx];
    g_h1[idx] = v > 0.f ? v : 0.f;
}

// ---------------- host-side layer driver ----------------
static void run_layer(const float* h_in, const int* src, const int* dst,
                      const float* W, const float* al, const float* ar,
                      const float* loop_w, const float* bias, int H, int Dh,
                      float* acc, bool do_relu) {
    const int mdTotal = RR * NN * H;

    pack_Bt<<<(COLS * DIN + 255) / 256, 256>>>(W, loop_w);
    gemm_mma<<<dim3(COLS / 128, (NN + 127) / 128), 256, GEMM_SMEM>>>(h_in, NN);
    init_acc<<<(NN * DIN + 255) / 256, 256>>>(bias, acc);
    init_den<<<(mdTotal + 255) / 256, 256>>>(mdTotal);
    elr_kernel<<<dim3(NN, RR), 128>>>(al, ar, H, Dh);
    edge_pass_exp<<<(RR * EE + 255) / 256, 256>>>(src, dst, H);
    rcp_den<<<(mdTotal + 255) / 256, 256>>>(mdTotal);
    {
        long long threads = (long long)RR * EE * 32;
        int blocks = (int)((threads + 255) / 256);
        edge_aggregate<<<blocks, 256>>>(src, dst, acc, H, Dh);
    }
    if (do_relu) relu_h1<<<(NN * DIN + 255) / 256, 256>>>();
}

extern "C" void kernel_launch(void* const* d_in, const int* in_sizes, int n_in,
                              void* d_out, int out_size) {
    const float* h   = (const float*)d_in[0];
    const int*   src = (const int*)d_in[1];
    const int*   dst = (const int*)d_in[2];
    const float* W1  = (const float*)d_in[3];
    const float* al1 = (const float*)d_in[4];
    const float* ar1 = (const float*)d_in[5];
    const float* lp1 = (const float*)d_in[6];
    const float* b1  = (const float*)d_in[7];
    const float* W2  = (const float*)d_in[8];
    const float* al2 = (const float*)d_in[9];
    const float* ar2 = (const float*)d_in[10];
    const float* lp2 = (const float*)d_in[11];
    const float* b2  = (const float*)d_in[12];
    float* out = (float*)d_out;

    static bool attr_set = false;
    if (!attr_set) {
        cudaFuncSetAttribute(gemm_mma, cudaFuncAttributeMaxDynamicSharedMemorySize, GEMM_SMEM);
        attr_set = true;
    }

    // Layer 1: h -> g_h1 (H=8, Dh=16), relu
    run_layer(h, src, dst, W1, al1, ar1, lp1, b1, 8, 16, nullptr, true);
    // Layer 2: g_h1 -> out (H=1, Dh=128), no activation
    run_layer(nullptr, src, dst, W2, al2, ar2, lp2, b2, 1, 128, out, false);

    (void)in_sizes; (void)n_in; (void)out_size;
}

// round 4
// speedup vs baseline: 2.3260x; 1.8327x over previous
#include <cuda_runtime.h>
#include <cstdint>

// Problem constants (fixed by the dataset)
#define NN   100000
#define EE   400000
#define RR   4
#define DIN  128
#define COLS 640         // R*128 + 128 self-loop
#define HMAX 8
#define NBUK (RR * NN)   // CSR buckets

// ---------------- device scratch (static, no allocation) ----------------
__device__ float g_Bt[COLS * DIN];            // packed weights [c][k], tf32-rounded
__device__ float g_WhAll[(size_t)NN * COLS];  // GEMM output   [N,640]
__device__ float g_h1[(size_t)NN * DIN];      // layer-1 output
__device__ float g_el[(size_t)RR * NN * HMAX];
__device__ float g_er[(size_t)RR * NN * HMAX];
// CSR
__device__ int g_cnt[NBUK];
__device__ int g_off[NBUK + 1];
__device__ int g_cur[NBUK];
__device__ int g_bsum[1024];
__device__ int g_esrc[RR * EE];               // src node per edge, bucketed by (r,dst)

// ---------------- helpers ----------------
__device__ __forceinline__ float tf32_rn(float x) {
    uint32_t u;
    asm("cvt.rna.tf32.f32 %0, %1;" : "=r"(u) : "f"(x));
    return __uint_as_float(u);
}
__device__ __forceinline__ void mma_tf32(float* d, const uint32_t* a, const uint32_t* b) {
    asm volatile(
        "mma.sync.aligned.m16n8k8.row.col.f32.tf32.tf32.f32 "
        "{%0,%1,%2,%3}, {%4,%5,%6,%7}, {%8,%9}, {%0,%1,%2,%3};"
        : "+f"(d[0]), "+f"(d[1]), "+f"(d[2]), "+f"(d[3])
        : "r"(a[0]), "r"(a[1]), "r"(a[2]), "r"(a[3]), "r"(b[0]), "r"(b[1]));
}

// ================= CSR build =================
__global__ void zero_cnt() {
    int i = blockIdx.x * blockDim.x + threadIdx.x;
    if (i < NBUK) g_cnt[i] = 0;
}
__global__ void hist_dst(const int* __restrict__ dst) {
    int i = blockIdx.x * blockDim.x + threadIdx.x;
    if (i >= RR * EE) return;
    int r = i / EE;
    atomicAdd(&g_cnt[r * NN + dst[i]], 1);
}
__global__ __launch_bounds__(1024) void scan_blk() {
    __shared__ int s[1024];
    int t = threadIdx.x;
    int i = blockIdx.x * 1024 + t;
    int v = (i < NBUK) ? g_cnt[i] : 0;
    s[t] = v;
    __syncthreads();
#pragma unroll
    for (int off = 1; off < 1024; off <<= 1) {
        int u = (t >= off) ? s[t - off] : 0;
        __syncthreads();
        s[t] += u;
        __syncthreads();
    }
    if (i < NBUK) g_off[i] = s[t] - v;   // exclusive within block
    if (t == 1023) g_bsum[blockIdx.x] = s[1023];
}
__global__ __launch_bounds__(1024) void scan_part(int nb) {
    __shared__ int s[1024];
    int t = threadIdx.x;
    int v = (t < nb) ? g_bsum[t] : 0;
    s[t] = v;
    __syncthreads();
#pragma unroll
    for (int off = 1; off < 1024; off <<= 1) {
        int u = (t >= off) ? s[t - off] : 0;
        __syncthreads();
        s[t] += u;
        __syncthreads();
    }
    g_bsum[t] = s[t] - v;                // exclusive block offsets
}
__global__ void scan_fix() {
    int i = blockIdx.x * blockDim.x + threadIdx.x;
    if (i >= NBUK) return;
    int o = g_off[i] + g_bsum[i >> 10];
    g_off[i] = o;
    g_cur[i] = o;
    if (i == 0) g_off[NBUK] = RR * EE;
}
__global__ void scatter_src(const int* __restrict__ src, const int* __restrict__ dst) {
    int i = blockIdx.x * blockDim.x + threadIdx.x;
    if (i >= RR * EE) return;
    int r = i / EE;
    int pos = atomicAdd(&g_cur[r * NN + dst[i]], 1);
    g_esrc[pos] = src[i];
}

// ---------------- pack weights transposed: g_Bt[c][k], tf32-rounded ----------------
__global__ void pack_Bt(const float* __restrict__ W, const float* __restrict__ loop_w) {
    int idx = blockIdx.x * blockDim.x + threadIdx.x;
    if (idx >= COLS * DIN) return;
    int c = idx >> 7, k = idx & 127;
    float v;
    if (c < RR * 128) {
        int r = c >> 7, j = c & 127;
        v = W[((size_t)r << 14) + (size_t)k * 128 + j];
    } else {
        v = loop_w[(size_t)k * 128 + (c - RR * 128)];
    }
    g_Bt[idx] = tf32_rn(v);
}

// ---------------- tf32 mma GEMM: C[M,640] = A[M,128] * g_Bt^T ----------------
#define LDS_PITCH 132
#define GEMM_SMEM (2 * 128 * LDS_PITCH * 4)
__global__ __launch_bounds__(256, 1) void gemm_mma(const float* __restrict__ Ain, int M) {
    const float* A = Ain ? Ain : g_h1;
    extern __shared__ float sm[];
    float (*As)[LDS_PITCH] = (float(*)[LDS_PITCH])sm;
    float (*Bs)[LDS_PITCH] = (float(*)[LDS_PITCH])(sm + 128 * LDS_PITCH);

    int tid = threadIdx.x;
    int wid = tid >> 5, lane = tid & 31;
    int group = lane >> 2, tid4 = lane & 3;
    int warp_m = wid >> 1, warp_n = wid & 1;
    int bn = blockIdx.x, by = blockIdx.y;

    {
        int row = tid >> 1;
        int colb = (tid & 1) * 64;
        int grow = by * 128 + row;
        const float4* ap = (grow < M) ? (const float4*)(A + (size_t)grow * DIN + colb) : nullptr;
#pragma unroll
        for (int j = 0; j < 16; j++) {
            float4 v = ap ? __ldg(ap + j) : make_float4(0.f, 0.f, 0.f, 0.f);
            float4 t = make_float4(tf32_rn(v.x), tf32_rn(v.y), tf32_rn(v.z), tf32_rn(v.w));
            *(float4*)(&As[row][colb + j * 4]) = t;
        }
    }
    {
        int row = tid >> 1;
        int colb = (tid & 1) * 64;
        const float4* bp = (const float4*)(g_Bt + (size_t)(bn * 128 + row) * DIN + colb);
#pragma unroll
        for (int j = 0; j < 16; j++)
            *(float4*)(&Bs[row][colb + j * 4]) = __ldg(bp + j);
    }
    __syncthreads();

    float acc[2][8][4] = {};
    int m0 = warp_m * 32;
    int n0 = warp_n * 64;

#pragma unroll
    for (int ks = 0; ks < 16; ks++) {
        int k0 = ks * 8;
        uint32_t afr[2][4];
#pragma unroll
        for (int mt = 0; mt < 2; mt++) {
            int mr = m0 + mt * 16;
            afr[mt][0] = __float_as_uint(As[mr + group][k0 + tid4]);
            afr[mt][1] = __float_as_uint(As[mr + group + 8][k0 + tid4]);
            afr[mt][2] = __float_as_uint(As[mr + group][k0 + tid4 + 4]);
            afr[mt][3] = __float_as_uint(As[mr + group + 8][k0 + tid4 + 4]);
        }
#pragma unroll
        for (int nt = 0; nt < 8; nt++) {
            int nc = n0 + nt * 8;
            uint32_t bfr[2];
            bfr[0] = __float_as_uint(Bs[nc + group][k0 + tid4]);
            bfr[1] = __float_as_uint(Bs[nc + group][k0 + tid4 + 4]);
            mma_tf32(acc[0][nt], afr[0], bfr);
            mma_tf32(acc[1][nt], afr[1], bfr);
        }
    }

#pragma unroll
    for (int mt = 0; mt < 2; mt++) {
        int row = by * 128 + m0 + mt * 16 + group;
#pragma unroll
        for (int nt = 0; nt < 8; nt++) {
            int col = bn * 128 + n0 + nt * 8 + tid4 * 2;
            if (row < M)
                *(float2*)(g_WhAll + (size_t)row * COLS + col) =
                    make_float2(acc[mt][nt][0], acc[mt][nt][1]);
            if (row + 8 < M)
                *(float2*)(g_WhAll + (size_t)(row + 8) * COLS + col) =
                    make_float2(acc[mt][nt][2], acc[mt][nt][3]);
        }
    }
}

// ---------------- el/er: warp per (r,node) ----------------
template <int H>
__global__ __launch_bounds__(256) void elr_warp(const float* __restrict__ al,
                                                const float* __restrict__ ar) {
    int w = (blockIdx.x * blockDim.x + threadIdx.x) >> 5;
    int lane = threadIdx.x & 31;
    if (w >= RR * NN) return;
    int r = w / NN, i = w - r * NN;
    float4 v = *(const float4*)(g_WhAll + (size_t)i * COLS + r * 128 + lane * 4);
    float4 a = __ldg((const float4*)(al + r * 128 + lane * 4));
    float4 b = __ldg((const float4*)(ar + r * 128 + lane * 4));
    float sl = v.x * a.x + v.y * a.y + v.z * a.z + v.w * a.w;
    float sr = v.x * b.x + v.y * b.y + v.z * b.z + v.w * b.w;
    if (H == 8) {
        sl += __shfl_xor_sync(~0u, sl, 1);
        sr += __shfl_xor_sync(~0u, sr, 1);
        sl += __shfl_xor_sync(~0u, sl, 2);
        sr += __shfl_xor_sync(~0u, sr, 2);
        if ((lane & 3) == 0) {
            int head = lane >> 2;
            g_el[(size_t)w * 8 + head] = sl;
            g_er[(size_t)w * 8 + head] = sr;
        }
    } else {
#pragma unroll
        for (int o = 16; o > 0; o >>= 1) {
            sl += __shfl_xor_sync(~0u, sl, o);
            sr += __shfl_xor_sync(~0u, sr, o);
        }
        if (lane == 0) {
            g_el[w] = sl;
            g_er[w] = sr;
        }
    }
}

// ---------------- fused per-node kernel: softmax + aggregate + selfloop + bias (+relu)
template <int H>
__global__ __launch_bounds__(256) void node_fused(const float* __restrict__ bias,
                                                  float* __restrict__ outp, int do_relu) {
    float* out = outp ? outp : g_h1;
    int d = (blockIdx.x * blockDim.x + threadIdx.x) >> 5;
    int lane = threadIdx.x & 31;
    if (d >= NN) return;

    // self-loop + bias
    float4 acc = *(const float4*)(g_WhAll + (size_t)d * COLS + RR * 128 + lane * 4);
    float4 bb = __ldg((const float4*)(bias + lane * 4));
    acc.x += bb.x; acc.y += bb.y; acc.z += bb.z; acc.w += bb.w;

#pragma unroll
    for (int r = 0; r < RR; r++) {
        int base = r * NN + d;
        int start = g_off[base];
        int end = g_off[base + 1];
        if (start == end) continue;

        if (H == 8) {
            int hl = lane & 7;               // head handled in pass 1
            float er_l = g_er[(size_t)base * 8 + hl];
            float den = 0.f;
            for (int c = start + (lane >> 3); c < end; c += 4) {
                int s = __ldg(&g_esrc[c]);
                float e = __ldg(&g_el[((size_t)r * NN + s) * 8 + hl]) + er_l;
                e = e > 0.f ? e : 0.2f * e;
                den += expf(e);
            }
            den += __shfl_xor_sync(~0u, den, 8);
            den += __shfl_xor_sync(~0u, den, 16);   // lane holds den for head lane&7
            float rden = 1.0f / den;
            int hh = lane >> 2;                      // head owning this lane's 4 columns
            float rden_h = __shfl_sync(~0u, rden, hh);
            float er_h = __shfl_sync(~0u, er_l, hh);
            for (int c = start; c < end; c++) {
                int s = __ldg(&g_esrc[c]);
                float e = __ldg(&g_el[((size_t)r * NN + s) * 8 + hh]) + er_h;
                e = e > 0.f ? e : 0.2f * e;
                float alpha = expf(e) * rden_h;
                float4 w = *(const float4*)(g_WhAll + (size_t)s * COLS + r * 128 + lane * 4);
                acc.x += alpha * w.x;
                acc.y += alpha * w.y;
                acc.z += alpha * w.z;
                acc.w += alpha * w.w;
            }
        } else {
            float er_l = g_er[base];
            float den = 0.f;
            for (int c = start + lane; c < end; c += 32) {
                int s = __ldg(&g_esrc[c]);
                float e = __ldg(&g_el[(size_t)r * NN + s]) + er_l;
                e = e > 0.f ? e : 0.2f * e;
                den += expf(e);
            }
#pragma unroll
            for (int o = 16; o > 0; o >>= 1) den += __shfl_xor_sync(~0u, den, o);
            float rden = 1.0f / den;
            for (int c = start; c < end; c++) {
                int s = __ldg(&g_esrc[c]);
                float e = __ldg(&g_el[(size_t)r * NN + s]) + er_l;
                e = e > 0.f ? e : 0.2f * e;
                float alpha = expf(e) * rden;
                float4 w = *(const float4*)(g_WhAll + (size_t)s * COLS + r * 128 + lane * 4);
                acc.x += alpha * w.x;
                acc.y += alpha * w.y;
                acc.z += alpha * w.z;
                acc.w += alpha * w.w;
            }
        }
    }

    if (do_relu) {
        acc.x = fmaxf(acc.x, 0.f);
        acc.y = fmaxf(acc.y, 0.f);
        acc.z = fmaxf(acc.z, 0.f);
        acc.w = fmaxf(acc.w, 0.f);
    }
    *(float4*)(out + (size_t)d * DIN + lane * 4) = acc;
}

extern "C" void kernel_launch(void* const* d_in, const int* in_sizes, int n_in,
                              void* d_out, int out_size) {
    const float* h   = (const float*)d_in[0];
    const int*   src = (const int*)d_in[1];
    const int*   dst = (const int*)d_in[2];
    const float* W1  = (const float*)d_in[3];
    const float* al1 = (const float*)d_in[4];
    const float* ar1 = (const float*)d_in[5];
    const float* lp1 = (const float*)d_in[6];
    const float* b1  = (const float*)d_in[7];
    const float* W2  = (const float*)d_in[8];
    const float* al2 = (const float*)d_in[9];
    const float* ar2 = (const float*)d_in[10];
    const float* lp2 = (const float*)d_in[11];
    const float* b2  = (const float*)d_in[12];
    float* out = (float*)d_out;

    static bool attr_set = false;
    if (!attr_set) {
        cudaFuncSetAttribute(gemm_mma, cudaFuncAttributeMaxDynamicSharedMemorySize, GEMM_SMEM);
        attr_set = true;
    }

    const int nb1 = (NBUK + 1023) / 1024;

    // ---- CSR build (graph shared by both layers) ----
    zero_cnt<<<(NBUK + 255) / 256, 256>>>();
    hist_dst<<<(RR * EE + 255) / 256, 256>>>(dst);
    scan_blk<<<nb1, 1024>>>();
    scan_part<<<1, 1024>>>(nb1);
    scan_fix<<<(NBUK + 255) / 256, 256>>>();
    scatter_src<<<(RR * EE + 255) / 256, 256>>>(src, dst);

    // ---- Layer 1 (H=8), relu -> g_h1 ----
    pack_Bt<<<(COLS * DIN + 255) / 256, 256>>>(W1, lp1);
    gemm_mma<<<dim3(COLS / 128, (NN + 127) / 128), 256, GEMM_SMEM>>>(h, NN);
    elr_warp<8><<<(RR * NN * 32 + 255) / 256, 256>>>(al1, ar1);
    node_fused<8><<<(NN * 32 + 255) / 256, 256>>>(b1, nullptr, 1);

    // ---- Layer 2 (H=1), no activation -> out ----
    pack_Bt<<<(COLS * DIN + 255) / 256, 256>>>(W2, lp2);
    gemm_mma<<<dim3(COLS / 128, (NN + 127) / 128), 256, GEMM_SMEM>>>(nullptr, NN);
    elr_warp<1><<<(RR * NN * 32 + 255) / 256, 256>>>(al2, ar2);
    node_fused<1><<<(NN * 32 + 255) / 256, 256>>>(b2, out, 0);

    (void)in_sizes; (void)n_in; (void)out_size;
}